// round 9
// baseline (speedup 1.0000x reference)
#include <cuda_runtime.h>
#include <cuda_fp16.h>

// Problem constants
#define NC     5
#define NB     128000
#define BATCH  8
#define NJ     15
#define HH     128
#define WW     240
#define HMPIX  (HH*WW)        // 30720 pixels per (b,cam,j) heatmap

// Tiling: 512 threads (16 warps), 3 CTAs/SM (smem 61.9KB, 42 regs) = 48 warps.
#define THREADS 512
#define BPT     25            // bins per thread
#define CHUNK   (THREADS*BPT) // 12800 bins per CTA
#define NCHUNK  (NB/CHUNK)    // 10 chunks -> grid 10 x 15 x 8 = 1200 CTAs
#define FILL_IT (HMPIX/4/THREADS)  // 15, exact
#define SPAIRS  (HMPIX + WW)  // pair entries incl. zero pad row = 30960

// Fused 8-byte per-(cam,bin) record (shared across all b,j):
//   .x = off (bits 0..15) | t_half_bits (bits 16..31)
//   .y = half2(vA, vB)  -- x-weights with border cases AND the u8 scale
//                          (1/255) folded in.
// Gather on the u8-pair heatmap su[] (2 bytes per pixel):
//   su[p] = (q[y][x], q[y][x+1]) with q = round(255*hm); col x+1 OOB -> 0;
//   row HH is a zero pad row (handles y1 OOB).
//   p0 = pair su[off] (row y0), p1 = pair su[off+WW] (row y0+1)
//   result = (vA,vB) . ( p0 + t*(p1-p0) )
__device__ uint2 g_rec[NC*NB];

__device__ __forceinline__ uint2 make_record(float gx, float gy) {
    // align_corners=True mapping
    float ix = (gx + 1.0f) * 0.5f * (float)(WW - 1);
    float iy = (gy + 1.0f) * 0.5f * (float)(HH - 1);
    float x0f = floorf(ix), y0f = floorf(iy);
    float fx = ix - x0f,    fy = iy - y0f;
    int   x0 = (int)x0f,    y0 = (int)y0f;

    float wA, wB; int xc;
    if (x0 >= 0 && x0 < WW) { xc = x0; wA = 1.0f - fx; wB = fx;  }
    else if (x0 == -1)      { xc = 0;  wA = fx;        wB = 0.f; }
    else                    { xc = 0;  wA = 0.f;       wB = 0.f; }

    float t, s; int yc;
    if (y0 >= 0 && y0 < HH) { yc = y0; t = fy;  s = 1.f; }
    else if (y0 == -1)      { yc = 0;  t = 0.f; s = fy;  }
    else                    { yc = 0;  t = 0.f; s = 0.f; }

    unsigned int off = (unsigned int)(yc * WW + xc);   // <= 30719
    __half th = __float2half_rn(t);
    const float inv255 = 1.0f / 255.0f;
    __half2 v = __floats2half2_rn(wA * s * inv255, wB * s * inv255);

    uint2 r;
    r.x = off | ((unsigned int)__half_as_ushort(th) << 16);
    r.y = *reinterpret_cast<unsigned int*>(&v);
    return r;
}

__global__ void prep_kernel(const float* __restrict__ grid) {
    int p = blockIdx.x * 256 + threadIdx.x;   // record pair index
    if (p >= NC * NB / 2) return;
    float4 g = reinterpret_cast<const float4*>(grid)[p];
    g_rec[p * 2]     = make_record(g.x, g.y);
    g_rec[p * 2 + 1] = make_record(g.z, g.w);
}

__device__ __forceinline__ unsigned int pack_u8x4(float4 v) {
    unsigned int q0 = __float2uint_rn(v.x * 255.f);
    unsigned int q1 = __float2uint_rn(v.y * 255.f);
    unsigned int q2 = __float2uint_rn(v.z * 255.f);
    unsigned int q3 = __float2uint_rn(v.w * 255.f);
    return q0 | (q1 << 8) | (q2 << 16) | (q3 << 24);
}

__global__ __launch_bounds__(THREADS, 3)
void sample_kernel(const float* __restrict__ heatmaps,
                   float* __restrict__ out) {
    // u8-pair heatmap: 30960 x u16 = 61,920 bytes (3 CTAs/SM fit in 228KB).
    extern __shared__ unsigned short su[];

    const int tid   = threadIdx.x;
    const int chunk = blockIdx.x;
    const int j     = blockIdx.y;
    const int b     = blockIdx.z;
    const int base  = chunk * CHUNK;

    // Zero the pad row (row HH) once.
    if (tid < WW) su[HMPIX + tid] = 0;

    // Fill x coord (column of this thread's float4's first pixel).
    // Step per iteration: (THREADS*4) % WW = 2048 % 240 = 128.
    const int xstart = (tid * 4) % WW;

    float acc[BPT];
#pragma unroll
    for (int k = 0; k < BPT; ++k) acc[k] = 0.f;

    const __half2 BIAS = __half2half2(__ushort_as_half((unsigned short)0x6400));

    for (int cam = 0; cam < NC; ++cam) {
        __syncthreads();  // previous gathers done (pad row visible, iter 0)

        // Fill u8-pair heatmap: per iter 1 LDG.128 (4 px, same row; 240%4==0
        // so never crosses a row), neighbor byte via shfl, 1 STS.64 (4 pairs).
        const float*  hm  = heatmaps + (((size_t)b * NC + cam) * NJ + j) * (size_t)HMPIX;
        const float4* hm4 = reinterpret_cast<const float4*>(hm);
        int x = xstart;
#pragma unroll 5
        for (int it = 0; it < FILL_IT; ++it) {
            int p = tid + it * THREADS;
            float4 v = __ldg(hm4 + p);
            unsigned int qa = pack_u8x4(v);
            unsigned int qn = __shfl_down_sync(0xffffffffu, qa, 1);
            if ((tid & 31) == 31 && x != WW - 4)
                qn = __float2uint_rn(__ldg(hm + 4 * p + 4) * 255.f);
            if (x == WW - 4) qn = 0u;    // pair (239, OOB) -> zero second byte

            // pairs: [q0,q1][q1,q2][q2,q3][q3,q4]
            uint2 st;
            st.x = __byte_perm(qa, qn, 0x2110);  // (q0,q1, q1,q2)
            st.y = __byte_perm(qa, qn, 0x4332);  // (q2,q3, q3,q4)
            reinterpret_cast<uint2*>(su)[p] = st;  // byte offset p*8, aligned

            x += 128;
            if (x >= WW) x -= WW;
        }
        __syncthreads();

        const uint2* __restrict__ rp = g_rec + cam * NB + base;

#pragma unroll
        for (int k = 0; k < BPT; ++k) {
            int i = k * THREADS + tid;
            uint2 r = __ldg(rp + i);
            unsigned int off = r.x & 0xFFFFu;
            __half2 t2  = __half2half2(__ushort_as_half((unsigned short)(r.x >> 16)));
            __half2 v01 = *reinterpret_cast<const __half2*>(&r.y);

            unsigned int a32 = (unsigned int)su[off];        // LDS.U16 row y0
            unsigned int b32 = (unsigned int)su[off + WW];   // LDS.U16 row y1
            unsigned int p0u = __byte_perm(a32, 0x64646464u, 0x4140); // (1024+q00,1024+q01)
            unsigned int p1u = __byte_perm(b32, 0x64646464u, 0x4140); // (1024+q10,1024+q11)
            __half2 p0b = *reinterpret_cast<const __half2*>(&p0u);
            __half2 p1b = *reinterpret_cast<const __half2*>(&p1u);
            __half2 d   = __hsub2(p1b, p0b);   // biases cancel; exact ints
            __half2 p0  = __hsub2(p0b, BIAS);  // exact integers 0..255
            __half2 pl  = __hfma2(d, t2, p0);  // row lerp
            __half2 pr  = __hmul2(pl, v01);    // x weights (incl. 1/255)
            float2 f    = __half22float2(pr);
            acc[k] += f.x + f.y;               // fp32 accumulation
        }
    }

    float* o = out + ((size_t)(b * NJ + j)) * NB + base;
#pragma unroll
    for (int k = 0; k < BPT; ++k) {
        float v = acc[k] * 0.2f;                          // mean over 5 cams
        o[k * THREADS + tid] = fminf(fmaxf(v, 0.f), 1.f); // clip [0,1]
    }
}

extern "C" void kernel_launch(void* const* d_in, const int* in_sizes, int n_in,
                              void* d_out, int out_size) {
    const float* heatmaps = (const float*)d_in[0];
    const float* grid     = (const float*)d_in[1];
    if (n_in >= 2 && in_sizes[0] == NC * NB * 2) {
        grid     = (const float*)d_in[0];
        heatmaps = (const float*)d_in[1];
    }

    const int smem_bytes = SPAIRS * (int)sizeof(unsigned short);  // 61,920 B
    cudaFuncSetAttribute(sample_kernel,
                         cudaFuncAttributeMaxDynamicSharedMemorySize, smem_bytes);

    prep_kernel<<<(NC * NB / 2 + 255) / 256, 256>>>(grid);

    dim3 g(NCHUNK, NJ, BATCH);
    sample_kernel<<<g, THREADS, smem_bytes>>>(heatmaps, (float*)d_out);
}

// round 10
// speedup vs baseline: 1.3466x; 1.3466x over previous
#include <cuda_runtime.h>
#include <cuda_fp16.h>

// Problem constants
#define NC     5
#define NB     128000
#define BATCH  8
#define NJ     15
#define HH     128
#define WW     240
#define HMPIX  (HH*WW)        // 30720 pixels per (b,cam,j) heatmap

// Tiling: 1024 threads, grid 600 (measured optimum). Double-buffered u8-pair
// heatmaps: 2 x 61,920 B = 123,840 B smem -> 1 CTA/SM, 32 warps, but fill of
// cam k+1 overlaps gather of cam k (fill DRAM/L2 latency hides under LDS).
#define THREADS 1024
#define BPT     25            // bins per thread
#define CHUNK   (THREADS*BPT) // 25600 bins per CTA
#define NCHUNK  (NB/CHUNK)    // 5 chunks -> grid 5 x 15 x 8 = 600 CTAs
#define FILL_IT 8             // ceil(7680/1024); iter 7 guard tid<512 (warp-uniform)
#define SPAIRS  (HMPIX + WW)  // u16 pair entries incl. zero pad row = 30960

// Fused 8-byte per-(cam,bin) record (shared across all b,j):
//   .x = off (bits 0..15) | t_half_bits (bits 16..31)
//   .y = half2(vA, vB)  -- x-weights with border cases and the u8 scale
//                          (1/255) folded in.
// Gather on a u8-pair heatmap buffer su[] (2 bytes per pixel):
//   su[p] = (q[y][x], q[y][x+1]), q = round(255*hm); col x+1 OOB -> 0;
//   row HH is a zero pad row (handles y1 OOB).
//   p0 = su[off] (row y0), p1 = su[off+WW] (row y0+1)
//   result = (vA,vB) . ( p0 + t*(p1-p0) )
__device__ uint2 g_rec[NC*NB];

__device__ __forceinline__ uint2 make_record(float gx, float gy) {
    // align_corners=True mapping
    float ix = (gx + 1.0f) * 0.5f * (float)(WW - 1);
    float iy = (gy + 1.0f) * 0.5f * (float)(HH - 1);
    float x0f = floorf(ix), y0f = floorf(iy);
    float fx = ix - x0f,    fy = iy - y0f;
    int   x0 = (int)x0f,    y0 = (int)y0f;

    float wA, wB; int xc;
    if (x0 >= 0 && x0 < WW) { xc = x0; wA = 1.0f - fx; wB = fx;  }
    else if (x0 == -1)      { xc = 0;  wA = fx;        wB = 0.f; }
    else                    { xc = 0;  wA = 0.f;       wB = 0.f; }

    float t, s; int yc;
    if (y0 >= 0 && y0 < HH) { yc = y0; t = fy;  s = 1.f; }
    else if (y0 == -1)      { yc = 0;  t = 0.f; s = fy;  }
    else                    { yc = 0;  t = 0.f; s = 0.f; }

    unsigned int off = (unsigned int)(yc * WW + xc);   // <= 30719
    __half th = __float2half_rn(t);
    const float inv255 = 1.0f / 255.0f;
    __half2 v = __floats2half2_rn(wA * s * inv255, wB * s * inv255);

    uint2 r;
    r.x = off | ((unsigned int)__half_as_ushort(th) << 16);
    r.y = *reinterpret_cast<unsigned int*>(&v);
    return r;
}

__global__ void prep_kernel(const float* __restrict__ grid) {
    int p = blockIdx.x * 256 + threadIdx.x;   // record pair index
    if (p >= NC * NB / 2) return;
    float4 g = reinterpret_cast<const float4*>(grid)[p];
    g_rec[p * 2]     = make_record(g.x, g.y);
    g_rec[p * 2 + 1] = make_record(g.z, g.w);
}

__device__ __forceinline__ unsigned int pack_u8x4(float4 v) {
    unsigned int q0 = __float2uint_rn(v.x * 255.f);
    unsigned int q1 = __float2uint_rn(v.y * 255.f);
    unsigned int q2 = __float2uint_rn(v.z * 255.f);
    unsigned int q3 = __float2uint_rn(v.w * 255.f);
    return q0 | (q1 << 8) | (q2 << 16) | (q3 << 24);
}

__global__ __launch_bounds__(THREADS, 1)
void sample_kernel(const float* __restrict__ heatmaps,
                   float* __restrict__ out) {
    // Two u8-pair heatmap buffers, 30960 u16 each (61,920 B; total 123,840 B).
    extern __shared__ unsigned short su[];

    const int tid   = threadIdx.x;
    const int chunk = blockIdx.x;
    const int j     = blockIdx.y;
    const int b     = blockIdx.z;
    const int base  = chunk * CHUNK;

    // Zero both buffers' pad rows once.
    if (tid < WW) { su[HMPIX + tid] = 0; su[SPAIRS + HMPIX + tid] = 0; }

    // Fill x coord of this thread's float4's first pixel; per-iteration
    // pixel step = 4096 -> x step = 4096 % 240 = 16.
    const int xstart = (tid * 4) % WW;
    const bool lane31 = ((tid & 31) == 31);

    const float* hmbase = heatmaps + (((size_t)b * NC) * NJ + j) * (size_t)HMPIX;
    const size_t camstride = (size_t)NJ * HMPIX;   // per-cam stride for fixed (b,j)

    float acc[BPT];
#pragma unroll
    for (int k = 0; k < BPT; ++k) acc[k] = 0.f;

    const __half2 BIAS = __half2half2(__ushort_as_half((unsigned short)0x6400));

    // ---- Prologue: fill cam 0 into buffer 0 ----
    {
        const float*  hm  = hmbase;
        const float4* hm4 = reinterpret_cast<const float4*>(hm);
        int x = xstart;
#pragma unroll
        for (int it = 0; it < FILL_IT; ++it) {
            int q = tid + it * THREADS;
            if (q < HMPIX / 4) {                       // warp-uniform guard
                float4 v = __ldg(hm4 + q);
                unsigned int qa = pack_u8x4(v);
                unsigned int qn = __shfl_down_sync(0xffffffffu, qa, 1);
                if (lane31 && x != WW - 4)
                    qn = __float2uint_rn(__ldg(hm + 4 * q + 4) * 255.f);
                if (x == WW - 4) qn = 0u;
                uint2 st;
                st.x = __byte_perm(qa, qn, 0x2110);    // (q0,q1, q1,q2)
                st.y = __byte_perm(qa, qn, 0x4332);    // (q2,q3, q3,q4)
                reinterpret_cast<uint2*>(su)[q] = st;
            }
            x += 16; if (x >= WW) x -= WW;
        }
    }
    __syncthreads();

    // ---- Pipelined cam loop: gather cam from cur, fill cam+1 into nxt ----
    for (int cam = 0; cam < NC; ++cam) {
        const unsigned short* cur = su + (cam & 1) * SPAIRS;
        unsigned short*       nxt = su + ((cam + 1) & 1) * SPAIRS;
        const bool have_next = (cam + 1 < NC);

        // Stage next cam's heatmap: LDG.128s issued here, packed to regs.
        // Their global-memory latency hides under the gather below.
        unsigned int qa_s[FILL_IT];
        unsigned int qn_s[FILL_IT];   // lane31's neighbor byte (others unused)
        if (have_next) {
            const float*  hm  = hmbase + (size_t)(cam + 1) * camstride;
            const float4* hm4 = reinterpret_cast<const float4*>(hm);
            int x = xstart;
#pragma unroll
            for (int it = 0; it < FILL_IT; ++it) {
                int q = tid + it * THREADS;
                if (q < HMPIX / 4) {
                    float4 v = __ldg(hm4 + q);
                    qa_s[it] = pack_u8x4(v);
                    qn_s[it] = 0u;
                    if (lane31 && x != WW - 4)
                        qn_s[it] = __float2uint_rn(__ldg(hm + 4 * q + 4) * 255.f);
                }
                x += 16; if (x >= WW) x -= WW;
            }
        }

        // Gather current cam (LDS-bound; overlaps the staged LDGs above).
        const uint2* __restrict__ rp = g_rec + cam * NB + base;
#pragma unroll
        for (int k = 0; k < BPT; ++k) {
            int i = k * THREADS + tid;
            uint2 r = __ldg(rp + i);
            unsigned int off = r.x & 0xFFFFu;
            __half2 t2  = __half2half2(__ushort_as_half((unsigned short)(r.x >> 16)));
            __half2 v01 = *reinterpret_cast<const __half2*>(&r.y);

            unsigned int a32 = (unsigned int)cur[off];        // LDS.U16 row y0
            unsigned int b32 = (unsigned int)cur[off + WW];   // LDS.U16 row y1
            unsigned int p0u = __byte_perm(a32, 0x64646464u, 0x4140);
            unsigned int p1u = __byte_perm(b32, 0x64646464u, 0x4140);
            __half2 p0b = *reinterpret_cast<const __half2*>(&p0u);
            __half2 p1b = *reinterpret_cast<const __half2*>(&p1u);
            __half2 d   = __hsub2(p1b, p0b);   // exact (biases cancel)
            __half2 p0  = __hsub2(p0b, BIAS);  // exact ints 0..255
            __half2 pl  = __hfma2(d, t2, p0);  // row lerp
            __half2 pr  = __hmul2(pl, v01);    // x weights (incl. 1/255)
            float2 f    = __half22float2(pr);
            acc[k] += f.x + f.y;               // fp32 accumulation
        }

        // Write staged pairs into the next buffer, then one barrier.
        if (have_next) {
            int x = xstart;
#pragma unroll
            for (int it = 0; it < FILL_IT; ++it) {
                int q = tid + it * THREADS;
                if (q < HMPIX / 4) {               // warp-uniform guard
                    unsigned int qa = qa_s[it];
                    unsigned int qn = __shfl_down_sync(0xffffffffu, qa, 1);
                    if (lane31) qn = qn_s[it];
                    if (x == WW - 4) qn = 0u;
                    uint2 st;
                    st.x = __byte_perm(qa, qn, 0x2110);
                    st.y = __byte_perm(qa, qn, 0x4332);
                    reinterpret_cast<uint2*>(nxt)[q] = st;
                }
                x += 16; if (x >= WW) x -= WW;
            }
            __syncthreads();
        }
    }

    float* o = out + ((size_t)(b * NJ + j)) * NB + base;
#pragma unroll
    for (int k = 0; k < BPT; ++k) {
        float v = acc[k] * 0.2f;                          // mean over 5 cams
        o[k * THREADS + tid] = fminf(fmaxf(v, 0.f), 1.f); // clip [0,1]
    }
}

extern "C" void kernel_launch(void* const* d_in, const int* in_sizes, int n_in,
                              void* d_out, int out_size) {
    const float* heatmaps = (const float*)d_in[0];
    const float* grid     = (const float*)d_in[1];
    if (n_in >= 2 && in_sizes[0] == NC * NB * 2) {
        grid     = (const float*)d_in[0];
        heatmaps = (const float*)d_in[1];
    }

    const int smem_bytes = 2 * SPAIRS * (int)sizeof(unsigned short); // 123,840 B
    cudaFuncSetAttribute(sample_kernel,
                         cudaFuncAttributeMaxDynamicSharedMemorySize, smem_bytes);

    prep_kernel<<<(NC * NB / 2 + 255) / 256, 256>>>(grid);

    dim3 g(NCHUNK, NJ, BATCH);
    sample_kernel<<<g, THREADS, smem_bytes>>>(heatmaps, (float*)d_out);
}